// round 15
// baseline (speedup 1.0000x reference)
#include <cuda_runtime.h>
#include <cuda_fp16.h>
#include <math.h>
#include <stdint.h>

// ---------------- problem constants ----------------
#define BATCH   256
#define FRAMES  4
#define LTOK    20
#define NTOK    81
#define EMBED   768
#define HEADS   12
#define HDIM    64
#define DEPTH   12
#define FEAT    2048
#define XROW    2054
#define M_ALL   (BATCH * NTOK)          // 20736
#define M_SPAT  (BATCH * FRAMES * LTOK) // 20480
#define OUTD    256

#define OFF_OBJ  0L
#define OFF_QKV  1572864L
#define OFF_AP   22806528L
#define OFF_FC1  29884416L
#define OFF_FC2  58195968L
#define OFF_PROJ 86507520L
#define W_TOTAL  86704128L

// ---------------- scratch ----------------
__device__ float g_X[M_ALL * EMBED];
__device__ float g_S[M_ALL * 4 * EMBED];   // fp32 embed tmp; fp16 view reused for qkv
__device__ float g_MB[M_ALL];
__device__ __half g_A16[63700992];         // M_ALL*3072 (embed input / fc1 out)
__device__ __half g_B16[M_ALL * EMBED];    // 768-wide activations
__device__ __half g_W16[W_TOTAL];

// ---------------- helpers ----------------
__device__ __forceinline__ uint32_t smem_u32(const void* p) {
    uint32_t a;
    asm("{ .reg .u64 t; cvta.to.shared.u64 t, %1; cvt.u32.u64 %0, t; }" : "=r"(a) : "l"(p));
    return a;
}
__device__ __forceinline__ void cpa16(uint32_t dst, const void* src) {
    asm volatile("cp.async.cg.shared.global [%0], [%1], 16;" :: "r"(dst), "l"(src));
}
__device__ __forceinline__ void ldsm4(uint32_t* r, uint32_t addr) {
    asm volatile("ldmatrix.sync.aligned.m8n8.x4.shared.b16 {%0,%1,%2,%3}, [%4];"
                 : "=r"(r[0]), "=r"(r[1]), "=r"(r[2]), "=r"(r[3]) : "r"(addr));
}
__device__ __forceinline__ void mma_f16(float* c, const uint32_t* a, const uint32_t* b) {
    asm volatile(
        "mma.sync.aligned.m16n8k16.row.col.f32.f16.f16.f32 "
        "{%0,%1,%2,%3}, {%4,%5,%6,%7}, {%8,%9}, {%0,%1,%2,%3};"
        : "+f"(c[0]), "+f"(c[1]), "+f"(c[2]), "+f"(c[3])
        : "r"(a[0]), "r"(a[1]), "r"(a[2]), "r"(a[3]), "r"(b[0]), "r"(b[1]));
}
__device__ __forceinline__ float gelu_exact(float x) {
    return 0.5f * x * (1.0f + erff(x * 0.70710678118654752f));
}

// KC=64 tile: rows x 64 halfs = 128B/row; swizzle g ^ (r&7) (proven conflict-free)
__device__ __forceinline__ uint32_t tile64_off(int r, int g) {
    return (uint32_t)((r << 7) + ((g ^ (r & 7)) << 4));
}

// -- fp16 GEMM, 128x256 CTA tile, 8 warps of 64x64, KC=64, 3 stages, 1 CTA/SM --------
#define KC 64
#define STAGES 3
#define STAGE_BYTES 49152  // A 16KB + B 32KB

template<int ACT, int ACC, int OSPLIT>
__global__ void __launch_bounds__(256, 1) gemm_mma(
    const __half* __restrict__ A16, int lda,
    const __half* __restrict__ B16, int ldw,
    const float* __restrict__ bias, float* __restrict__ C,
    __half* __restrict__ O16, int ldc, int K)
{
    extern __shared__ char smem[];
    const uint32_t sbase = smem_u32(smem);
    const int tid = threadIdx.x, wid = tid >> 5, lane = tid & 31;
    const int row0 = blockIdx.y * 128, col0 = blockIdx.x * 256;
    const int warp_m = (wid & 1) * 64, warp_n = (wid >> 1) * 64;

    const __half* gA = A16 + (long)row0 * lda;
    const __half* gB = B16 + (long)col0 * ldw;

    float acc[4][8][4];
    #pragma unroll
    for (int a = 0; a < 4; a++)
        #pragma unroll
        for (int b = 0; b < 8; b++)
            #pragma unroll
            for (int c = 0; c < 4; c++) acc[a][b][c] = 0.0f;

    const int id  = lane >> 3;
    const int rin = lane & 7;
    const int a_row = warp_m + ((id & 1) << 3) + rin;
    const int b_row = warp_n + ((id >> 1) << 3) + rin;
    const int ag = id >> 1;
    const int bg = id & 1;

    // loaders: A 1024 chunks (4/thread), B 2048 chunks (8/thread)
    int      la_row[4];  uint32_t la_off[4];
    #pragma unroll
    for (int i = 0; i < 4; i++) {
        const int c_ = tid + i * 256;
        la_row[i] = c_ >> 3;
        la_off[i] = tile64_off(la_row[i], c_ & 7);
    }
    int      lb_row[8];  uint32_t lb_off[8];
    #pragma unroll
    for (int i = 0; i < 8; i++) {
        const int c_ = tid + i * 256;
        lb_row[i] = c_ >> 3;
        lb_off[i] = tile64_off(lb_row[i], c_ & 7);
    }
    const int l_g = tid & 7;

    const int nk = K / KC;

#define LOAD_STAGE(stage, k0)                                                            \
    {                                                                                    \
        const uint32_t st_ = sbase + (stage) * STAGE_BYTES;                              \
        _Pragma("unroll")                                                                \
        for (int i = 0; i < 4; i++)                                                      \
            cpa16(st_ + la_off[i],         gA + (long)la_row[i] * lda + (k0) + l_g * 8); \
        _Pragma("unroll")                                                                \
        for (int i = 0; i < 8; i++)                                                      \
            cpa16(st_ + 16384 + lb_off[i], gB + (long)lb_row[i] * ldw + (k0) + l_g * 8); \
        asm volatile("cp.async.commit_group;" ::: "memory");                             \
    }

    LOAD_STAGE(0, 0);
    if (nk > 1) LOAD_STAGE(1, KC);

    for (int ck = 0; ck < nk; ck++) {
        if (ck + 1 < nk) {
            asm volatile("cp.async.wait_group 1;" ::: "memory");
        } else {
            asm volatile("cp.async.wait_group 0;" ::: "memory");
        }
        __syncthreads();
        if (ck + 2 < nk) LOAD_STAGE((ck + 2) % STAGES, (ck + 2) * KC);

        const uint32_t st = sbase + (ck % STAGES) * STAGE_BYTES;
        const uint32_t sA_ = st, sB_ = st + 16384;

        #pragma unroll
        for (int ks = 0; ks < 4; ks++) {
            uint32_t bf[4][4];
            #pragma unroll
            for (int ntp = 0; ntp < 4; ntp++)
                ldsm4(bf[ntp], sB_ + tile64_off(b_row + ntp * 16, 2 * ks + bg));
            #pragma unroll
            for (int mt = 0; mt < 4; mt++) {
                uint32_t af[4];
                ldsm4(af, sA_ + tile64_off(a_row + mt * 16, 2 * ks + ag));
                #pragma unroll
                for (int nt = 0; nt < 8; nt++)
                    mma_f16(acc[mt][nt], af, &bf[nt >> 1][(nt & 1) * 2]);
            }
        }
    }
#undef LOAD_STAGE

    #pragma unroll
    for (int mt = 0; mt < 4; mt++) {
        #pragma unroll
        for (int nt = 0; nt < 8; nt++) {
            const int r = row0 + warp_m + mt * 16 + (lane >> 2);
            const int c = col0 + warp_n + nt * 8 + (lane & 3) * 2;
            const float b0 = bias ? bias[c] : 0.0f;
            const float b1 = bias ? bias[c + 1] : 0.0f;
            #pragma unroll
            for (int h = 0; h < 2; h++) {
                const long rr = r + h * 8;
                float v0 = acc[mt][nt][h * 2 + 0] + b0;
                float v1 = acc[mt][nt][h * 2 + 1] + b1;
                if (ACT) { v0 = gelu_exact(v0); v1 = gelu_exact(v1); }
                if (ACC) {
                    float2 old = *(const float2*)&C[rr * ldc + c];
                    v0 += old.x; v1 += old.y;
                    float2 nv = {v0, v1};
                    *(float2*)&C[rr * ldc + c] = nv;
                } else if (OSPLIT) {
                    __half2 hv = {__float2half(v0), __float2half(v1)};
                    *(__half2*)&O16[rr * ldc + c] = hv;
                } else {
                    float2 nv = {v0, v1};
                    *(float2*)&C[rr * ldc + c] = nv;
                }
            }
        }
    }
}

// ---------------- fp32 -> fp16 convert ----------------
__global__ void __launch_bounds__(256) split_k(
    const float* __restrict__ in, __half* __restrict__ o16, long n)
{
    for (long i = blockIdx.x * 256L + threadIdx.x; i < n; i += gridDim.x * 256L)
        o16[i] = __float2half(in[i]);
}
__global__ void __launch_bounds__(256) split_x_k(
    const float* __restrict__ in, __half* __restrict__ o16)
{
    const long n = (long)M_SPAT * FEAT;
    for (long i = blockIdx.x * 256L + threadIdx.x; i < n; i += gridDim.x * 256L) {
        const long r = i >> 11, c = i & 2047;
        o16[i] = __float2half(in[r * XROW + c]);
    }
}

// ---------------- LayerNorm -> fp16 ----------------
__global__ void __launch_bounds__(256) ln_k(
    const float* __restrict__ X, const float* __restrict__ w,
    const float* __restrict__ b, __half* __restrict__ Y16)
{
    const long t = blockIdx.x;
    const float* xr = X + t * EMBED;
    const int tid = threadIdx.x;

    float v0 = xr[tid], v1 = xr[tid + 256], v2 = xr[tid + 512];
    float s  = v0 + v1 + v2;
    float ss = v0 * v0 + v1 * v1 + v2 * v2;

    __shared__ float red[16];
    for (int o = 16; o; o >>= 1) {
        s  += __shfl_xor_sync(0xffffffffu, s,  o);
        ss += __shfl_xor_sync(0xffffffffu, ss, o);
    }
    const int warp = tid >> 5, lane = tid & 31;
    if (lane == 0) { red[warp] = s; red[warp + 8] = ss; }
    __syncthreads();
    __shared__ float smean, srstd;
    if (tid == 0) {
        float S = 0, SS = 0;
        #pragma unroll
        for (int i = 0; i < 8; i++) { S += red[i]; SS += red[i + 8]; }
        float m   = S * (1.0f / EMBED);
        float var = SS * (1.0f / EMBED) - m * m;
        smean = m;
        srstd = rsqrtf(var + 1e-6f);
    }
    __syncthreads();
    const float m = smean, r = srstd;
    Y16[t * EMBED + tid]       = __float2half((v0 - m) * r * w[tid]       + b[tid]);
    Y16[t * EMBED + tid + 256] = __float2half((v1 - m) * r * w[tid + 256] + b[tid + 256]);
    Y16[t * EMBED + tid + 512] = __float2half((v2 - m) * r * w[tid + 512] + b[tid + 512]);
}

// ---------------- frame-local attention (fp16 QKV): block per (batch, frame, head) ----
__global__ void __launch_bounds__(128) attn_frame_k(
    const __half* __restrict__ QKV, const float* __restrict__ MB,
    __half* __restrict__ O16)
{
    __shared__ float Qs[LTOK * HDIM];
    __shared__ float Ks[(LTOK + 1) * HDIM];
    __shared__ float Vs[(LTOK + 1) * HDIM];
    __shared__ float mbs[LTOK + 1];
    __shared__ float probs[4][LTOK + 1];

    const int bid = blockIdx.x;
    const int h  = bid % HEADS;
    const int bf = bid / HEADS;
    const int f  = bf % FRAMES, b = bf / FRAMES;
    const int tid = threadIdx.x;
    const long base = (long)b * NTOK * (3 * EMBED);

    for (int idx = tid; idx < LTOK * HDIM; idx += 128) {
        const int i = idx >> 6, c = idx & 63;
        Qs[idx] = __half2float(QKV[base + (long)(1 + f * LTOK + i) * (3 * EMBED) + h * HDIM + c]) * 0.125f;
    }
    for (int idx = tid; idx < (LTOK + 1) * HDIM; idx += 128) {
        const int j = idx >> 6, c = idx & 63;
        const int tok = (j == 0) ? 0 : (1 + f * LTOK + j - 1);
        const long p = base + (long)tok * (3 * EMBED) + h * HDIM + c;
        Ks[idx] = __half2float(QKV[p + EMBED]);
        Vs[idx] = __half2float(QKV[p + 2 * EMBED]);
    }
    if (tid < LTOK + 1) {
        const int tok = (tid == 0) ? 0 : (1 + f * LTOK + tid - 1);
        mbs[tid] = MB[b * NTOK + tok];
    }
    __syncthreads();

    const int w = tid >> 5, lane = tid & 31;
    for (int i = w; i < LTOK; i += 4) {
        float sim = -1e30f;
        if (lane < LTOK + 1) {
            const float* q = Qs + i * HDIM;
            const float* k = Ks + lane * HDIM;
            float d = 0.0f;
            #pragma unroll
            for (int c = 0; c < HDIM; c++) d = fmaf(q[c], k[c], d);
            sim = d + mbs[lane];
        }
        float mx = sim;
        for (int o = 16; o; o >>= 1) mx = fmaxf(mx, __shfl_xor_sync(0xffffffffu, mx, o));
        float p = (lane < LTOK + 1) ? expf(sim - mx) : 0.0f;
        float lsum = p;
        for (int o = 16; o; o >>= 1) lsum += __shfl_xor_sync(0xffffffffu, lsum, o);
        if (lane < LTOK + 1) probs[w][lane] = p;
        const float inv = 1.0f / lsum;
        __syncwarp();

        float o0 = 0.0f, o1 = 0.0f;
        const int c0 = lane * 2;
        for (int t = 0; t < LTOK + 1; t++) {
            const float pp = probs[w][t];
            o0 = fmaf(pp, Vs[t * HDIM + c0],     o0);
            o1 = fmaf(pp, Vs[t * HDIM + c0 + 1], o1);
        }
        const long oi = ((long)(b * NTOK + 1 + f * LTOK + i)) * EMBED + h * HDIM + c0;
        O16[oi]     = __float2half(o0 * inv);
        O16[oi + 1] = __float2half(o1 * inv);
        __syncwarp();
    }
}

// ---------------- cls attention (fp16 QKV): one warp per (batch, head) ----------------
__global__ void __launch_bounds__(32) attn_cls_k(
    const __half* __restrict__ QKV, const float* __restrict__ MB,
    __half* __restrict__ O16)
{
    __shared__ float q[HDIM];
    __shared__ float probs[NTOK];

    const int bid = blockIdx.x;
    const int h = bid % HEADS, b = bid / HEADS;
    const int lane = threadIdx.x;
    const long base = (long)b * NTOK * (3 * EMBED);
    const long hoff = h * HDIM;

    q[lane]      = __half2float(QKV[base + hoff + lane]) * 0.125f;
    q[lane + 32] = __half2float(QKV[base + hoff + lane + 32]) * 0.125f;
    __syncwarp();

    float sims[3];
    float mx = -1e30f;
    int s = 0;
    for (int t = lane; t < NTOK; t += 32, s++) {
        const __half* kk = QKV + base + (long)t * (3 * EMBED) + EMBED + hoff;
        float d = 0.0f;
        #pragma unroll
        for (int c = 0; c < HDIM; c++) d = fmaf(q[c], __half2float(kk[c]), d);
        sims[s] = d + MB[b * NTOK + t];
        mx = fmaxf(mx, sims[s]);
    }
    for (int o = 16; o; o >>= 1) mx = fmaxf(mx, __shfl_xor_sync(0xffffffffu, mx, o));
    float lsum = 0.0f;
    s = 0;
    for (int t = lane; t < NTOK; t += 32, s++) {
        const float p = expf(sims[s] - mx);
        probs[t] = p;
        lsum += p;
    }
    for (int o = 16; o; o >>= 1) lsum += __shfl_xor_sync(0xffffffffu, lsum, o);
    const float inv = 1.0f / lsum;
    __syncwarp();

    float o0 = 0.0f, o1 = 0.0f;
    const int c0 = lane * 2;
    for (int t = 0; t < NTOK; t++) {
        const float p = probs[t];
        const __half* vv = QKV + base + (long)t * (3 * EMBED) + 2 * EMBED + hoff;
        o0 = fmaf(p, __half2float(vv[c0]),     o0);
        o1 = fmaf(p, __half2float(vv[c0 + 1]), o1);
    }
    const long oi = ((long)(b * NTOK)) * EMBED + hoff + c0;
    O16[oi]     = __float2half(o0 * inv);
    O16[oi + 1] = __float2half(o1 * inv);
}

// ---------------- embed epilogue ----------------
__global__ void __launch_bounds__(256) embed_finish_k(
    const float* __restrict__ S, const float* __restrict__ x,
    const float* __restrict__ objb, const float* __restrict__ posb,
    const float* __restrict__ posW, const float* __restrict__ te,
    const int* __restrict__ xmask, float* __restrict__ X, float* __restrict__ MB)
{
    const int t = blockIdx.x;
    const int b = t / (FRAMES * LTOK);
    const int j = t % (FRAMES * LTOK);
    const int f = j / LTOK;

    __shared__ float xp[6];
    if (threadIdx.x < 6) xp[threadIdx.x] = x[(long)t * XROW + FEAT + threadIdx.x];
    __syncthreads();

    const long orow = ((long)b * NTOK + 1 + j) * EMBED;
    for (int e = threadIdx.x; e < EMBED; e += 256) {
        float v = S[(long)t * EMBED + e] + objb[e] + posb[e] + te[f * EMBED + e];
        #pragma unroll
        for (int k = 0; k < 6; k++) v = fmaf(xp[k], posW[e * 6 + k], v);
        X[orow + e] = v;
    }
    if (threadIdx.x == 0) MB[b * NTOK + 1 + j] = xmask[t] ? 0.0f : -100.0f;
}

__global__ void __launch_bounds__(256) cls_init_k(
    const float* __restrict__ cls_tok, const float* __restrict__ cls_pos,
    float* __restrict__ X, float* __restrict__ MB)
{
    const int b = blockIdx.x;
    for (int e = threadIdx.x; e < EMBED; e += 256)
        X[(long)b * NTOK * EMBED + e] = cls_tok[e] + cls_pos[e];
    if (threadIdx.x == 0) MB[b * NTOK] = 0.0f;
}

__global__ void __launch_bounds__(256) copy_mbias_k(
    const float* __restrict__ MB, float* __restrict__ out)
{
    const int i = blockIdx.x * 256 + threadIdx.x;
    if (i < M_ALL) out[i] = MB[i];
}

// ---------------- host orchestration ----------------
#define GEMM_SMEM (STAGES * STAGE_BYTES)   // 147456

extern "C" void kernel_launch(void* const* d_in, const int* in_sizes, int n_in,
                              void* d_out, int out_size)
{
    const float* x        = (const float*)d_in[0];
    const int*   x_mask   = (const int*)  d_in[1];
    const float* obj_W    = (const float*)d_in[2];
    const float* obj_b    = (const float*)d_in[3];
    const float* pos_W    = (const float*)d_in[4];
    const float* pos_b    = (const float*)d_in[5];
    const float* cls_tok  = (const float*)d_in[6];
    const float* cls_pos  = (const float*)d_in[7];
    const float* temporal = (const float*)d_in[8];
    const float* ln1_w    = (const float*)d_in[9];
    const float* ln1_b    = (const float*)d_in[10];
    const float* ln2_w    = (const float*)d_in[11];
    const float* ln2_b    = (const float*)d_in[12];
    const float* qkv_W    = (const float*)d_in[13];
    const float* qkv_b    = (const float*)d_in[14];
    const float* ap_W     = (const float*)d_in[15];
    const float* ap_b     = (const float*)d_in[16];
    const float* fc1_W    = (const float*)d_in[17];
    const float* fc1_b    = (const float*)d_in[18];
    const float* fc2_W    = (const float*)d_in[19];
    const float* fc2_b    = (const float*)d_in[20];
    const float* proj_W   = (const float*)d_in[21];

    float *gX, *gS, *gM;
    __half *gA16, *gB16, *gW16;
    cudaGetSymbolAddress((void**)&gX, g_X);
    cudaGetSymbolAddress((void**)&gS, g_S);
    cudaGetSymbolAddress((void**)&gM, g_MB);
    cudaGetSymbolAddress((void**)&gA16, g_A16);
    cudaGetSymbolAddress((void**)&gB16, g_B16);
    cudaGetSymbolAddress((void**)&gW16, g_W16);
    __half* gS16 = (__half*)gS;

    cudaFuncSetAttribute(gemm_mma<0,0,0>, cudaFuncAttributeMaxDynamicSharedMemorySize, GEMM_SMEM);
    cudaFuncSetAttribute(gemm_mma<0,1,0>, cudaFuncAttributeMaxDynamicSharedMemorySize, GEMM_SMEM);
    cudaFuncSetAttribute(gemm_mma<1,0,1>, cudaFuncAttributeMaxDynamicSharedMemorySize, GEMM_SMEM);
    cudaFuncSetAttribute(gemm_mma<0,0,1>, cudaFuncAttributeMaxDynamicSharedMemorySize, GEMM_SMEM);

    // ---- conversions; launches 5/6 are gemm halves ----
    split_x_k<<<2048, 256>>>(x, gA16);
    split_k<<<2048, 256>>>(obj_W,  gW16 + OFF_OBJ,  (long)EMBED * FEAT);
    split_k<<<2048, 256>>>(qkv_W,  gW16 + OFF_QKV,  (long)DEPTH * 3 * EMBED * EMBED);
    split_k<<<2048, 256>>>(ap_W,   gW16 + OFF_AP,   (long)DEPTH * EMBED * EMBED);
    gemm_mma<0,0,0><<<dim3(EMBED / 256, 80), 256, GEMM_SMEM>>>(
        gA16, FEAT, gW16 + OFF_OBJ, FEAT, nullptr, gS, nullptr, EMBED, FEAT);
    gemm_mma<0,0,0><<<dim3(EMBED / 256, 80), 256, GEMM_SMEM>>>(
        gA16 + (long)80 * 128 * FEAT, FEAT, gW16 + OFF_OBJ, FEAT, nullptr,
        gS + (long)80 * 128 * EMBED, nullptr, EMBED, FEAT);
    split_k<<<2048, 256>>>(fc1_W,  gW16 + OFF_FC1,  (long)DEPTH * 4 * EMBED * EMBED);
    split_k<<<2048, 256>>>(fc2_W,  gW16 + OFF_FC2,  (long)DEPTH * EMBED * 4 * EMBED);
    split_k<<<2048, 256>>>(proj_W, gW16 + OFF_PROJ, (long)OUTD * EMBED);
    embed_finish_k<<<M_SPAT, 256>>>(gS, x, obj_b, pos_b, pos_W, temporal, x_mask, gX, gM);
    cls_init_k<<<BATCH, 256>>>(cls_tok, cls_pos, gX, gM);

    // ---- layers ----
    for (int l = 0; l < DEPTH; l++) {
        const long oq = OFF_QKV + (long)l * 3 * EMBED * EMBED;
        const long oa = OFF_AP  + (long)l * EMBED * EMBED;
        const long o1 = OFF_FC1 + (long)l * 4 * EMBED * EMBED;
        const long o2 = OFF_FC2 + (long)l * EMBED * 4 * EMBED;
        const float* qb  = qkv_b + (long)l * 3 * EMBED;
        const float* ab  = ap_b  + (long)l * EMBED;
        const float* f1b = fc1_b + (long)l * 4 * EMBED;
        const float* f2b = fc2_b + (long)l * EMBED;

        ln_k<<<M_ALL, 256>>>(gX, ln1_w + l * EMBED, ln1_b + l * EMBED, gB16);
        gemm_mma<0,0,1><<<dim3(3 * EMBED / 256, M_ALL / 128), 256, GEMM_SMEM>>>(
            gB16, EMBED, gW16 + oq, EMBED, qb, nullptr, gS16, 3 * EMBED, EMBED);
        attn_frame_k<<<BATCH * FRAMES * HEADS, 128>>>(gS16, gM, gB16);
        attn_cls_k<<<BATCH * HEADS, 32>>>(gS16, gM, gB16);
        gemm_mma<0,1,0><<<dim3(EMBED / 256, M_ALL / 128), 256, GEMM_SMEM>>>(
            gB16, EMBED, gW16 + oa, EMBED, ab, gX, nullptr, EMBED, EMBED);
        ln_k<<<M_ALL, 256>>>(gX, ln2_w + l * EMBED, ln2_b + l * EMBED, gB16);
        gemm_mma<1,0,1><<<dim3(4 * EMBED / 256, M_ALL / 128), 256, GEMM_SMEM>>>(
            gB16, EMBED, gW16 + o1, EMBED, f1b, nullptr, gA16, 4 * EMBED, EMBED);
        gemm_mma<0,1,0><<<dim3(EMBED / 256, M_ALL / 128), 256, GEMM_SMEM>>>(
            gA16, 4 * EMBED, gW16 + o2, 4 * EMBED, f2b, gX, nullptr, EMBED, 4 * EMBED);
    }

    // ---- head ----
    float* out = (float*)d_out;
    split_k<<<2048, 256>>>(gX, gB16, (long)M_ALL * EMBED);
    gemm_mma<0,0,0><<<dim3(OUTD / 256, M_ALL / 128), 256, GEMM_SMEM>>>(
        gB16, EMBED, gW16 + OFF_PROJ, EMBED, nullptr, out, nullptr, OUTD, EMBED);

    if (out_size >= M_ALL * OUTD + M_ALL) {
        copy_mbias_k<<<(M_ALL + 255) / 256, 256>>>(gM, out + (long)M_ALL * OUTD);
    }
}

// round 16
// speedup vs baseline: 1.1882x; 1.1882x over previous
#include <cuda_runtime.h>
#include <cuda_fp16.h>
#include <math.h>
#include <stdint.h>

// ---------------- problem constants ----------------
#define BATCH   256
#define FRAMES  4
#define LTOK    20
#define NTOK    81
#define EMBED   768
#define HEADS   12
#define HDIM    64
#define DEPTH   12
#define FEAT    2048
#define XROW    2054
#define M_ALL   (BATCH * NTOK)          // 20736
#define M_SPAT  (BATCH * FRAMES * LTOK) // 20480
#define OUTD    256

#define OFF_OBJ  0L
#define OFF_QKV  1572864L
#define OFF_AP   22806528L
#define OFF_FC1  29884416L
#define OFF_FC2  58195968L
#define OFF_PROJ 86507520L
#define W_TOTAL  86704128L

// ---------------- scratch ----------------
__device__ float g_X[M_ALL * EMBED];
__device__ float g_S[M_ALL * 4 * EMBED];   // fp32 embed tmp; fp16 view reused for qkv
__device__ float g_MB[M_ALL];
__device__ __half g_A16[63700992];         // M_ALL*3072 (embed input / fc1 out)
__device__ __half g_B16[M_ALL * EMBED];    // 768-wide activations
__device__ __half g_W16[W_TOTAL];

// ---------------- helpers ----------------
__device__ __forceinline__ uint32_t smem_u32(const void* p) {
    uint32_t a;
    asm("{ .reg .u64 t; cvta.to.shared.u64 t, %1; cvt.u32.u64 %0, t; }" : "=r"(a) : "l"(p));
    return a;
}
__device__ __forceinline__ void cpa16(uint32_t dst, const void* src) {
    asm volatile("cp.async.cg.shared.global [%0], [%1], 16;" :: "r"(dst), "l"(src));
}
__device__ __forceinline__ void ldsm4(uint32_t* r, uint32_t addr) {
    asm volatile("ldmatrix.sync.aligned.m8n8.x4.shared.b16 {%0,%1,%2,%3}, [%4];"
                 : "=r"(r[0]), "=r"(r[1]), "=r"(r[2]), "=r"(r[3]) : "r"(addr));
}
__device__ __forceinline__ void mma_f16(float* c, const uint32_t* a, const uint32_t* b) {
    asm volatile(
        "mma.sync.aligned.m16n8k16.row.col.f32.f16.f16.f32 "
        "{%0,%1,%2,%3}, {%4,%5,%6,%7}, {%8,%9}, {%0,%1,%2,%3};"
        : "+f"(c[0]), "+f"(c[1]), "+f"(c[2]), "+f"(c[3])
        : "r"(a[0]), "r"(a[1]), "r"(a[2]), "r"(a[3]), "r"(b[0]), "r"(b[1]));
}
__device__ __forceinline__ float gelu_exact(float x) {
    return 0.5f * x * (1.0f + erff(x * 0.70710678118654752f));
}

// KC=64 tile: 128 rows x 64 halfs = 128B/row; swizzle g ^ (r&7) (proven conflict-free)
__device__ __forceinline__ uint32_t tile64_off(int r, int g) {
    return (uint32_t)((r << 7) + ((g ^ (r & 7)) << 4));
}

// ------ fp16 GEMM, 128x128 tile, 8 warps of 64x32, KC=64, 3 stages, 2 CTA/SM -------
#define KC 64
#define STAGES 3
#define STAGE_BYTES 32768  // A 16KB + B 16KB

template<int ACT, int ACC, int OSPLIT>
__global__ void __launch_bounds__(256, 2) gemm_mma(
    const __half* __restrict__ A16, int lda,
    const __half* __restrict__ B16, int ldw,
    const float* __restrict__ bias, float* __restrict__ C,
    __half* __restrict__ O16, int ldc, int K)
{
    extern __shared__ char smem[];
    const uint32_t sbase = smem_u32(smem);
    const int tid = threadIdx.x, wid = tid >> 5, lane = tid & 31;
    const int row0 = blockIdx.y * 128, col0 = blockIdx.x * 128;
    const int warp_m = (wid & 1) * 64, warp_n = (wid >> 1) * 32;

    const __half* gA = A16 + (long)row0 * lda;
    const __half* gB = B16 + (long)col0 * ldw;

    float acc[4][4][4];
    #pragma unroll
    for (int a = 0; a < 4; a++)
        #pragma unroll
        for (int b = 0; b < 4; b++)
            #pragma unroll
            for (int c = 0; c < 4; c++) acc[a][b][c] = 0.0f;

    const int id  = lane >> 3;
    const int rin = lane & 7;
    const int a_row = warp_m + ((id & 1) << 3) + rin;
    const int b_row = warp_n + ((id >> 1) << 3) + rin;
    const int ag = id >> 1;
    const int bg = id & 1;

    int      l_row[4];
    uint32_t l_off[4];
    #pragma unroll
    for (int i = 0; i < 4; i++) {
        const int c_ = tid + i * 256;
        l_row[i] = c_ >> 3;
        l_off[i] = tile64_off(l_row[i], c_ & 7);
    }
    const int l_g = tid & 7;

    const int nk = K / KC;

#define LOAD_STAGE(stage, k0)                                                           \
    {                                                                                   \
        const uint32_t st_ = sbase + (stage) * STAGE_BYTES;                             \
        _Pragma("unroll")                                                               \
        for (int i = 0; i < 4; i++) {                                                   \
            cpa16(st_ + l_off[i],         gA + (long)l_row[i] * lda + (k0) + l_g * 8);  \
            cpa16(st_ + 16384 + l_off[i], gB + (long)l_row[i] * ldw + (k0) + l_g * 8);  \
        }                                                                               \
        asm volatile("cp.async.commit_group;" ::: "memory");                            \
    }

    LOAD_STAGE(0, 0);
    if (nk > 1) LOAD_STAGE(1, KC);

    for (int ck = 0; ck < nk; ck++) {
        if (ck + 1 < nk) {
            asm volatile("cp.async.wait_group 1;" ::: "memory");
        } else {
            asm volatile("cp.async.wait_group 0;" ::: "memory");
        }
        __syncthreads();
        if (ck + 2 < nk) LOAD_STAGE((ck + 2) % STAGES, (ck + 2) * KC);

        const uint32_t st = sbase + (ck % STAGES) * STAGE_BYTES;
        const uint32_t sA_ = st, sB_ = st + 16384;

        #pragma unroll
        for (int ks = 0; ks < 4; ks++) {
            uint32_t bf[2][4];
            #pragma unroll
            for (int ntp = 0; ntp < 2; ntp++)
                ldsm4(bf[ntp], sB_ + tile64_off(b_row + ntp * 16, 2 * ks + bg));
            #pragma unroll
            for (int mt = 0; mt < 4; mt++) {
                uint32_t af[4];
                ldsm4(af, sA_ + tile64_off(a_row + mt * 16, 2 * ks + ag));
                #pragma unroll
                for (int nt = 0; nt < 4; nt++)
                    mma_f16(acc[mt][nt], af, &bf[nt >> 1][(nt & 1) * 2]);
            }
        }
    }
#undef LOAD_STAGE

    #pragma unroll
    for (int mt = 0; mt < 4; mt++) {
        #pragma unroll
        for (int nt = 0; nt < 4; nt++) {
            const int r = row0 + warp_m + mt * 16 + (lane >> 2);
            const int c = col0 + warp_n + nt * 8 + (lane & 3) * 2;
            const float b0 = bias ? bias[c] : 0.0f;
            const float b1 = bias ? bias[c + 1] : 0.0f;
            #pragma unroll
            for (int h = 0; h < 2; h++) {
                const long rr = r + h * 8;
                float v0 = acc[mt][nt][h * 2 + 0] + b0;
                float v1 = acc[mt][nt][h * 2 + 1] + b1;
                if (ACT) { v0 = gelu_exact(v0); v1 = gelu_exact(v1); }
                if (ACC) {
                    float2 old = *(const float2*)&C[rr * ldc + c];
                    v0 += old.x; v1 += old.y;
                    float2 nv = {v0, v1};
                    *(float2*)&C[rr * ldc + c] = nv;
                } else if (OSPLIT) {
                    __half2 hv = {__float2half(v0), __float2half(v1)};
                    *(__half2*)&O16[rr * ldc + c] = hv;
                } else {
                    float2 nv = {v0, v1};
                    *(float2*)&C[rr * ldc + c] = nv;
                }
            }
        }
    }
}

// ---------------- fp32 -> fp16 convert ----------------
__global__ void __launch_bounds__(256) split_k(
    const float* __restrict__ in, __half* __restrict__ o16, long n)
{
    for (long i = blockIdx.x * 256L + threadIdx.x; i < n; i += gridDim.x * 256L)
        o16[i] = __float2half(in[i]);
}
__global__ void __launch_bounds__(256) split_x_k(
    const float* __restrict__ in, __half* __restrict__ o16)
{
    const long n = (long)M_SPAT * FEAT;
    for (long i = blockIdx.x * 256L + threadIdx.x; i < n; i += gridDim.x * 256L) {
        const long r = i >> 11, c = i & 2047;
        o16[i] = __float2half(in[r * XROW + c]);
    }
}

// ---------------- LayerNorm -> fp16 : one WARP per token, shuffle-only reduce --------
__global__ void __launch_bounds__(256) ln_k(
    const float* __restrict__ X, const float* __restrict__ w,
    const float* __restrict__ b, __half* __restrict__ Y16)
{
    const int warp = threadIdx.x >> 5, lane = threadIdx.x & 31;
    const long t = (long)blockIdx.x * 8 + warp;     // grid = M_ALL/8 = 2592 exact
    const float* xr = X + t * EMBED;

    float4 v[6];
    float s = 0.0f, ss = 0.0f;
    #pragma unroll
    for (int j = 0; j < 6; j++) {
        v[j] = *(const float4*)&xr[(lane + 32 * j) * 4];
        s  += v[j].x + v[j].y + v[j].z + v[j].w;
        ss += v[j].x * v[j].x + v[j].y * v[j].y + v[j].z * v[j].z + v[j].w * v[j].w;
    }
    #pragma unroll
    for (int o = 16; o; o >>= 1) {
        s  += __shfl_xor_sync(0xffffffffu, s,  o);
        ss += __shfl_xor_sync(0xffffffffu, ss, o);
    }
    const float m = s * (1.0f / EMBED);
    const float r = rsqrtf(ss * (1.0f / EMBED) - m * m + 1e-6f);

    #pragma unroll
    for (int j = 0; j < 6; j++) {
        const int e = (lane + 32 * j) * 4;
        const float4 wv = *(const float4*)&w[e];
        const float4 bv = *(const float4*)&b[e];
        __half2 h0 = {__float2half((v[j].x - m) * r * wv.x + bv.x),
                      __float2half((v[j].y - m) * r * wv.y + bv.y)};
        __half2 h1 = {__float2half((v[j].z - m) * r * wv.z + bv.z),
                      __float2half((v[j].w - m) * r * wv.w + bv.w)};
        *(__half2*)&Y16[t * EMBED + e]     = h0;
        *(__half2*)&Y16[t * EMBED + e + 2] = h1;
    }
}

// ---------------- frame-local attention (fp16 QKV): block per (batch, frame, head) ----
__global__ void __launch_bounds__(128) attn_frame_k(
    const __half* __restrict__ QKV, const float* __restrict__ MB,
    __half* __restrict__ O16)
{
    __shared__ float Qs[LTOK * HDIM];
    __shared__ float Ks[(LTOK + 1) * HDIM];
    __shared__ float Vs[(LTOK + 1) * HDIM];
    __shared__ float mbs[LTOK + 1];
    __shared__ float probs[4][LTOK + 1];

    const int bid = blockIdx.x;
    const int h  = bid % HEADS;
    const int bf = bid / HEADS;
    const int f  = bf % FRAMES, b = bf / FRAMES;
    const int tid = threadIdx.x;
    const long base = (long)b * NTOK * (3 * EMBED);

    for (int idx = tid; idx < LTOK * HDIM; idx += 128) {
        const int i = idx >> 6, c = idx & 63;
        Qs[idx] = __half2float(QKV[base + (long)(1 + f * LTOK + i) * (3 * EMBED) + h * HDIM + c]) * 0.125f;
    }
    for (int idx = tid; idx < (LTOK + 1) * HDIM; idx += 128) {
        const int j = idx >> 6, c = idx & 63;
        const int tok = (j == 0) ? 0 : (1 + f * LTOK + j - 1);
        const long p = base + (long)tok * (3 * EMBED) + h * HDIM + c;
        Ks[idx] = __half2float(QKV[p + EMBED]);
        Vs[idx] = __half2float(QKV[p + 2 * EMBED]);
    }
    if (tid < LTOK + 1) {
        const int tok = (tid == 0) ? 0 : (1 + f * LTOK + tid - 1);
        mbs[tid] = MB[b * NTOK + tok];
    }
    __syncthreads();

    const int w = tid >> 5, lane = tid & 31;
    for (int i = w; i < LTOK; i += 4) {
        float sim = -1e30f;
        if (lane < LTOK + 1) {
            const float* q = Qs + i * HDIM;
            const float* k = Ks + lane * HDIM;
            float d = 0.0f;
            #pragma unroll
            for (int c = 0; c < HDIM; c++) d = fmaf(q[c], k[c], d);
            sim = d + mbs[lane];
        }
        float mx = sim;
        for (int o = 16; o; o >>= 1) mx = fmaxf(mx, __shfl_xor_sync(0xffffffffu, mx, o));
        float p = (lane < LTOK + 1) ? expf(sim - mx) : 0.0f;
        float lsum = p;
        for (int o = 16; o; o >>= 1) lsum += __shfl_xor_sync(0xffffffffu, lsum, o);
        if (lane < LTOK + 1) probs[w][lane] = p;
        const float inv = 1.0f / lsum;
        __syncwarp();

        float o0 = 0.0f, o1 = 0.0f;
        const int c0 = lane * 2;
        for (int t = 0; t < LTOK + 1; t++) {
            const float pp = probs[w][t];
            o0 = fmaf(pp, Vs[t * HDIM + c0],     o0);
            o1 = fmaf(pp, Vs[t * HDIM + c0 + 1], o1);
        }
        const long oi = ((long)(b * NTOK + 1 + f * LTOK + i)) * EMBED + h * HDIM + c0;
        O16[oi]     = __float2half(o0 * inv);
        O16[oi + 1] = __float2half(o1 * inv);
        __syncwarp();
    }
}

// ---------------- cls attention (fp16 QKV): one warp per (batch, head) ----------------
__global__ void __launch_bounds__(32) attn_cls_k(
    const __half* __restrict__ QKV, const float* __restrict__ MB,
    __half* __restrict__ O16)
{
    __shared__ float q[HDIM];
    __shared__ float probs[NTOK];

    const int bid = blockIdx.x;
    const int h = bid % HEADS, b = bid / HEADS;
    const int lane = threadIdx.x;
    const long base = (long)b * NTOK * (3 * EMBED);
    const long hoff = h * HDIM;

    q[lane]      = __half2float(QKV[base + hoff + lane]) * 0.125f;
    q[lane + 32] = __half2float(QKV[base + hoff + lane + 32]) * 0.125f;
    __syncwarp();

    float sims[3];
    float mx = -1e30f;
    int s = 0;
    for (int t = lane; t < NTOK; t += 32, s++) {
        const __half* kk = QKV + base + (long)t * (3 * EMBED) + EMBED + hoff;
        float d = 0.0f;
        #pragma unroll
        for (int c = 0; c < HDIM; c++) d = fmaf(q[c], __half2float(kk[c]), d);
        sims[s] = d + MB[b * NTOK + t];
        mx = fmaxf(mx, sims[s]);
    }
    for (int o = 16; o; o >>= 1) mx = fmaxf(mx, __shfl_xor_sync(0xffffffffu, mx, o));
    float lsum = 0.0f;
    s = 0;
    for (int t = lane; t < NTOK; t += 32, s++) {
        const float p = expf(sims[s] - mx);
        probs[t] = p;
        lsum += p;
    }
    for (int o = 16; o; o >>= 1) lsum += __shfl_xor_sync(0xffffffffu, lsum, o);
    const float inv = 1.0f / lsum;
    __syncwarp();

    float o0 = 0.0f, o1 = 0.0f;
    const int c0 = lane * 2;
    for (int t = 0; t < NTOK; t++) {
        const float p = probs[t];
        const __half* vv = QKV + base + (long)t * (3 * EMBED) + 2 * EMBED + hoff;
        o0 = fmaf(p, __half2float(vv[c0]),     o0);
        o1 = fmaf(p, __half2float(vv[c0 + 1]), o1);
    }
    const long oi = ((long)(b * NTOK)) * EMBED + hoff + c0;
    O16[oi]     = __float2half(o0 * inv);
    O16[oi + 1] = __float2half(o1 * inv);
}

// ---------------- embed epilogue ----------------
__global__ void __launch_bounds__(256) embed_finish_k(
    const float* __restrict__ S, const float* __restrict__ x,
    const float* __restrict__ objb, const float* __restrict__ posb,
    const float* __restrict__ posW, const float* __restrict__ te,
    const int* __restrict__ xmask, float* __restrict__ X, float* __restrict__ MB)
{
    const int t = blockIdx.x;
    const int b = t / (FRAMES * LTOK);
    const int j = t % (FRAMES * LTOK);
    const int f = j / LTOK;

    __shared__ float xp[6];
    if (threadIdx.x < 6) xp[threadIdx.x] = x[(long)t * XROW + FEAT + threadIdx.x];
    __syncthreads();

    const long orow = ((long)b * NTOK + 1 + j) * EMBED;
    for (int e = threadIdx.x; e < EMBED; e += 256) {
        float v = S[(long)t * EMBED + e] + objb[e] + posb[e] + te[f * EMBED + e];
        #pragma unroll
        for (int k = 0; k < 6; k++) v = fmaf(xp[k], posW[e * 6 + k], v);
        X[orow + e] = v;
    }
    if (threadIdx.x == 0) MB[b * NTOK + 1 + j] = xmask[t] ? 0.0f : -100.0f;
}

__global__ void __launch_bounds__(256) cls_init_k(
    const float* __restrict__ cls_tok, const float* __restrict__ cls_pos,
    float* __restrict__ X, float* __restrict__ MB)
{
    const int b = blockIdx.x;
    for (int e = threadIdx.x; e < EMBED; e += 256)
        X[(long)b * NTOK * EMBED + e] = cls_tok[e] + cls_pos[e];
    if (threadIdx.x == 0) MB[b * NTOK] = 0.0f;
}

__global__ void __launch_bounds__(256) copy_mbias_k(
    const float* __restrict__ MB, float* __restrict__ out)
{
    const int i = blockIdx.x * 256 + threadIdx.x;
    if (i < M_ALL) out[i] = MB[i];
}

// ---------------- host orchestration ----------------
#define GEMM_SMEM (STAGES * STAGE_BYTES)   // 98304

extern "C" void kernel_launch(void* const* d_in, const int* in_sizes, int n_in,
                              void* d_out, int out_size)
{
    const float* x        = (const float*)d_in[0];
    const int*   x_mask   = (const int*)  d_in[1];
    const float* obj_W    = (const float*)d_in[2];
    const float* obj_b    = (const float*)d_in[3];
    const float* pos_W    = (const float*)d_in[4];
    const float* pos_b    = (const float*)d_in[5];
    const float* cls_tok  = (const float*)d_in[6];
    const float* cls_pos  = (const float*)d_in[7];
    const float* temporal = (const float*)d_in[8];
    const float* ln1_w    = (const float*)d_in[9];
    const float* ln1_b    = (const float*)d_in[10];
    const float* ln2_w    = (const float*)d_in[11];
    const float* ln2_b    = (const float*)d_in[12];
    const float* qkv_W    = (const float*)d_in[13];
    const float* qkv_b    = (const float*)d_in[14];
    const float* ap_W     = (const float*)d_in[15];
    const float* ap_b     = (const float*)d_in[16];
    const float* fc1_W    = (const float*)d_in[17];
    const float* fc1_b    = (const float*)d_in[18];
    const float* fc2_W    = (const float*)d_in[19];
    const float* fc2_b    = (const float*)d_in[20];
    const float* proj_W   = (const float*)d_in[21];

    float *gX, *gS, *gM;
    __half *gA16, *gB16, *gW16;
    cudaGetSymbolAddress((void**)&gX, g_X);
    cudaGetSymbolAddress((void**)&gS, g_S);
    cudaGetSymbolAddress((void**)&gM, g_MB);
    cudaGetSymbolAddress((void**)&gA16, g_A16);
    cudaGetSymbolAddress((void**)&gB16, g_B16);
    cudaGetSymbolAddress((void**)&gW16, g_W16);
    __half* gS16 = (__half*)gS;

    cudaFuncSetAttribute(gemm_mma<0,0,0>, cudaFuncAttributeMaxDynamicSharedMemorySize, GEMM_SMEM);
    cudaFuncSetAttribute(gemm_mma<0,1,0>, cudaFuncAttributeMaxDynamicSharedMemorySize, GEMM_SMEM);
    cudaFuncSetAttribute(gemm_mma<1,0,1>, cudaFuncAttributeMaxDynamicSharedMemorySize, GEMM_SMEM);
    cudaFuncSetAttribute(gemm_mma<0,0,1>, cudaFuncAttributeMaxDynamicSharedMemorySize, GEMM_SMEM);

    // ---- conversions; launches 5/6 are gemm halves ----
    split_x_k<<<2048, 256>>>(x, gA16);
    split_k<<<2048, 256>>>(obj_W,  gW16 + OFF_OBJ,  (long)EMBED * FEAT);
    split_k<<<2048, 256>>>(qkv_W,  gW16 + OFF_QKV,  (long)DEPTH * 3 * EMBED * EMBED);
    split_k<<<2048, 256>>>(ap_W,   gW16 + OFF_AP,   (long)DEPTH * EMBED * EMBED);
    gemm_mma<0,0,0><<<dim3(EMBED / 128, 80), 256, GEMM_SMEM>>>(
        gA16, FEAT, gW16 + OFF_OBJ, FEAT, nullptr, gS, nullptr, EMBED, FEAT);
    gemm_mma<0,0,0><<<dim3(EMBED / 128, 80), 256, GEMM_SMEM>>>(
        gA16 + (long)80 * 128 * FEAT, FEAT, gW16 + OFF_OBJ, FEAT, nullptr,
        gS + (long)80 * 128 * EMBED, nullptr, EMBED, FEAT);
    split_k<<<2048, 256>>>(fc1_W,  gW16 + OFF_FC1,  (long)DEPTH * 4 * EMBED * EMBED);
    split_k<<<2048, 256>>>(fc2_W,  gW16 + OFF_FC2,  (long)DEPTH * EMBED * 4 * EMBED);
    split_k<<<2048, 256>>>(proj_W, gW16 + OFF_PROJ, (long)OUTD * EMBED);
    embed_finish_k<<<M_SPAT, 256>>>(gS, x, obj_b, pos_b, pos_W, temporal, x_mask, gX, gM);
    cls_init_k<<<BATCH, 256>>>(cls_tok, cls_pos, gX, gM);

    // ---- layers ----
    for (int l = 0; l < DEPTH; l++) {
        const long oq = OFF_QKV + (long)l * 3 * EMBED * EMBED;
        const long oa = OFF_AP  + (long)l * EMBED * EMBED;
        const long o1 = OFF_FC1 + (long)l * 4 * EMBED * EMBED;
        const long o2 = OFF_FC2 + (long)l * EMBED * 4 * EMBED;
        const float* qb  = qkv_b + (long)l * 3 * EMBED;
        const float* ab  = ap_b  + (long)l * EMBED;
        const float* f1b = fc1_b + (long)l * 4 * EMBED;
        const float* f2b = fc2_b + (long)l * EMBED;

        ln_k<<<M_ALL / 8, 256>>>(gX, ln1_w + l * EMBED, ln1_b + l * EMBED, gB16);
        gemm_mma<0,0,1><<<dim3(3 * EMBED / 128, M_ALL / 128), 256, GEMM_SMEM>>>(
            gB16, EMBED, gW16 + oq, EMBED, qb, nullptr, gS16, 3 * EMBED, EMBED);
        attn_frame_k<<<BATCH * FRAMES * HEADS, 128>>>(gS16, gM, gB16);
        attn_cls_k<<<BATCH * HEADS, 32>>>(gS16, gM, gB16);
        gemm_mma<0,1,0><<<dim3(EMBED / 128, M_ALL / 128), 256, GEMM_SMEM>>>(
            gB16, EMBED, gW16 + oa, EMBED, ab, gX, nullptr, EMBED, EMBED);
        ln_k<<<M_ALL / 8, 256>>>(gX, ln2_w + l * EMBED, ln2_b + l * EMBED, gB16);
        gemm_mma<1,0,1><<<dim3(4 * EMBED / 128, M_ALL / 128), 256, GEMM_SMEM>>>(
            gB16, EMBED, gW16 + o1, EMBED, f1b, nullptr, gA16, 4 * EMBED, EMBED);
        gemm_mma<0,1,0><<<dim3(EMBED / 128, M_ALL / 128), 256, GEMM_SMEM>>>(
            gA16, 4 * EMBED, gW16 + o2, 4 * EMBED, f2b, gX, nullptr, EMBED, 4 * EMBED);
    }

    // ---- head ----
    float* out = (float*)d_out;
    split_k<<<2048, 256>>>(gX, gB16, (long)M_ALL * EMBED);
    gemm_mma<0,0,0><<<dim3(OUTD / 128, M_ALL / 128), 256, GEMM_SMEM>>>(
        gB16, EMBED, gW16 + OFF_PROJ, EMBED, nullptr, out, nullptr, OUTD, EMBED);

    if (out_size >= M_ALL * OUTD + M_ALL) {
        copy_mbias_k<<<(M_ALL + 255) / 256, 256>>>(gM, out + (long)M_ALL * OUTD);
    }
}